// round 9
// baseline (speedup 1.0000x reference)
#include <cuda_runtime.h>
#include <cuda_bf16.h>
#include <cstdint>

// ============================================================================
// CandidateScorer — int8 fixed-point split MMA (m16n8k32.s8) + bulk staging.
//   scores = relu(relu(X W1 + b1) W2 + b2) W3 + b3
// Each operand quantized to 15 bits (per-row scale for X, per-col for W,
// fixed 1/2048 for H), split q = qh*128 + ql (two s8 planes). Dot product
// computed exactly as 2^14*Ah*Bh + 2^7*(Ah*Bl + Al*Bh) with two s32
// accumulator sets (Al*Bl dropped, ~1e-4 contribution).
// Operands pre-materialized in gmem as swizzled SMEM-images (128B rows =
// 128 int8 of K); GEMM stages 64KB chunks with 4 cp.async.bulk, 3 stages.
// GEMM2 fuses bias+relu+W3 into the epilogue (H2 never materialized).
// ============================================================================

#define N_CAND 65536
#define K1P    896              // K1=832 zero-padded to 7*128
#define HID    1024
#define BOARD_SQ 361

#define M_TILE 128
#define N_TILE 128
#define THREADS 256
#define NCH1   7                // 896 / 128
#define NCH2   8                // 1024 / 128
#define N_MT   (N_CAND / M_TILE)  // 512
#define N_NT   (HID / N_TILE)     // 8

#define IMG    16384            // 128 rows * 128 B (one s8 tile image)
#define STAGE_BYTES (4 * IMG)   // Ah | Al | Bh | Bl = 65536
#define N_STAGES 3
#define SMEM_TOTAL (1024 + N_STAGES * STAGE_BYTES)   // 197632

// ---------------------------------------------------------------------------
// Scratch (allocation-free rule: __device__ globals), all in tile-image form.
// ---------------------------------------------------------------------------
__device__ __align__(1024) unsigned char g_Xt_hi[(size_t)N_MT * NCH1 * IMG];
__device__ __align__(1024) unsigned char g_Xt_lo[(size_t)N_MT * NCH1 * IMG];
__device__ __align__(1024) unsigned char g_W1t_hi[(size_t)N_NT * NCH1 * IMG];
__device__ __align__(1024) unsigned char g_W1t_lo[(size_t)N_NT * NCH1 * IMG];
__device__ __align__(1024) unsigned char g_W2t_hi[(size_t)N_NT * NCH2 * IMG];
__device__ __align__(1024) unsigned char g_W2t_lo[(size_t)N_NT * NCH2 * IMG];
__device__ __align__(1024) unsigned char g_Ht_hi[(size_t)N_MT * NCH2 * IMG];
__device__ __align__(1024) unsigned char g_Ht_lo[(size_t)N_MT * NCH2 * IMG];
__device__ float g_pf_t[BOARD_SQ * 256];
__device__ float g_gpool[256];
__device__ float g_sxa[N_CAND];          // per-row dequant scale of X
__device__ float g_sw1[HID];             // per-col dequant scale of W1
__device__ float g_sw2[HID];             // per-col dequant scale of W2
__device__ float g_part[(size_t)N_NT * N_CAND];

#define H_QSCALE 2048.0f                 // fixed quant scale for H
#define H_DEQ    (1.0f / 2048.0f)
#define QMAX     16256                   // 127*128 (split-safe 15-bit range)

// ---------------------------------------------------------------------------
// PTX helpers (plain-target: cp.async.bulk / mbarrier / ldmatrix / mma.sync)
// ---------------------------------------------------------------------------
__device__ __forceinline__ uint32_t smem_u32(const void* p) {
    uint32_t a;
    asm("{ .reg .u64 t; cvta.to.shared.u64 t, %1; cvt.u32.u64 %0, t; }" : "=r"(a) : "l"(p));
    return a;
}

#define MBARRIER_INIT(mbar, cnt) \
    asm volatile("mbarrier.init.shared.b64 [%0], %1;" \
                 :: "r"((uint32_t)(mbar)), "r"((uint32_t)(cnt)) : "memory")
#define MBARRIER_EXPECT_TX(mbar, bytes) \
    asm volatile("mbarrier.arrive.expect_tx.shared.b64 _, [%0], %1;" \
                 :: "r"((uint32_t)(mbar)), "r"((uint32_t)(bytes)) : "memory")
#define FENCE_PROXY_ASYNC() \
    asm volatile("fence.proxy.async.shared::cta;" ::: "memory")

__device__ __forceinline__ void bulk_g2s(uint32_t dst, const void* src,
                                         uint32_t bytes, uint32_t mbar) {
    asm volatile(
        "cp.async.bulk.shared::cluster.global.mbarrier::complete_tx::bytes "
        "[%0], [%1], %2, [%3];"
        :: "r"(dst), "l"(__cvta_generic_to_global(src)), "r"(bytes), "r"(mbar)
        : "memory");
}

#define MBARRIER_WAIT_PARITY(mbar_smem_addr, phase_parity) do { \
    uint32_t _mbar = (uint32_t)(mbar_smem_addr); \
    uint32_t _parity = (uint32_t)(phase_parity); \
    uint32_t _done; \
    asm volatile( \
        "{\n\t.reg .pred p;\n\t" \
        "mbarrier.try_wait.parity.acquire.cta.shared::cta.b64 p, [%1], %2;\n\t" \
        "selp.b32 %0, 1, 0, p;\n\t}" \
        : "=r"(_done) : "r"(_mbar), "r"(_parity) : "memory"); \
    if (!_done) { \
        asm volatile( \
            "{\n\t.reg .pred P1;\n\t" \
            "WAIT_LOOP_%=:\n\t" \
            "mbarrier.try_wait.parity.acquire.cta.shared::cta.b64 P1, [%0], %1, 0x989680;\n\t" \
            "@P1 bra.uni WAIT_DONE_%=;\n\t" \
            "bra.uni WAIT_LOOP_%=;\n\t" \
            "WAIT_DONE_%=:\n\t}" \
            :: "r"(_mbar), "r"(_parity) : "memory"); \
    } \
} while (0)

__device__ __forceinline__ void ldsm_x4(uint32_t& r0, uint32_t& r1, uint32_t& r2,
                                        uint32_t& r3, uint32_t addr) {
    asm volatile("ldmatrix.sync.aligned.m8n8.x4.shared.b16 {%0,%1,%2,%3}, [%4];"
                 : "=r"(r0), "=r"(r1), "=r"(r2), "=r"(r3) : "r"(addr));
}

__device__ __forceinline__ void imma(int* c, uint32_t a0, uint32_t a1,
                                     uint32_t a2, uint32_t a3,
                                     uint32_t b0, uint32_t b1) {
    asm volatile(
        "mma.sync.aligned.m16n8k32.row.col.s32.s8.s8.s32 "
        "{%0,%1,%2,%3}, {%4,%5,%6,%7}, {%8,%9}, {%0,%1,%2,%3};"
        : "+r"(c[0]), "+r"(c[1]), "+r"(c[2]), "+r"(c[3])
        : "r"(a0), "r"(a1), "r"(a2), "r"(a3), "r"(b0), "r"(b1));
}

__device__ __forceinline__ uint32_t swz(uint32_t off) {      // SW128 pattern
    return off ^ ((off >> 3) & 0x70);
}

// q in [-QMAX, QMAX] -> (qh, ql) with q = qh*128 + ql, ql in [-64,63]
__device__ __forceinline__ void qsplit(int q, int& qh, int& ql) {
    ql = ((q + 64) & 127) - 64;
    qh = (q - ql) / 128;
}

// ---------------------------------------------------------------------------
// Prep 1: transpose policy map + global pool
// ---------------------------------------------------------------------------
__global__ void prep_pf_kernel(const float* __restrict__ pf) {
    int b = blockIdx.x, t = threadIdx.x;
    if (b < BOARD_SQ) {
        g_pf_t[b * 256 + t] = pf[(size_t)t * BOARD_SQ + b];   // pf_t[p][c]
    } else {                                                  // b == BOARD_SQ
        const float* p = pf + (size_t)t * BOARD_SQ;
        float s = 0.f;
        for (int i = 0; i < BOARD_SQ; i++) s += p[i];
        g_gpool[t] = s * (1.0f / 361.0f);
    }
}

// ---------------------------------------------------------------------------
// Prep 2: build X as quantized split-int8 tile images. Warp per candidate.
// Per-row scale: warp computes row absmax first.
// ---------------------------------------------------------------------------
__global__ void buildX_kernel(const float* __restrict__ cand) {
    int gw = (blockIdx.x * blockDim.x + threadIdx.x) >> 5;
    int lane = threadIdx.x & 31;
    if (gw >= N_CAND) return;
    const float* cf = cand + (size_t)gw * 64;
    int gr = min(max((int)(cf[5] * 18.0f), 0), 18);
    int gc = min(max((int)(cf[6] * 18.0f), 0), 18);
    int tr = min(max((int)(cf[7] * 18.0f), 0), 18);
    int tc = min(max((int)(cf[8] * 18.0f), 0), 18);
    int go = gr * 19 + gc, to = tr * 19 + tc;

    float vals[NCH1][4];
    float amax = 0.f;
    #pragma unroll
    for (int ch = 0; ch < NCH1; ch++) {
        #pragma unroll
        for (int q = 0; q < 4; q++) {
            int k = ch * 128 + lane * 4 + q;
            float v = 0.f;
            if (k < 256)       v = g_pf_t[go * 256 + k];
            else if (k < 512)  v = g_pf_t[to * 256 + (k - 256)];
            else if (k < 768)  v = g_gpool[k - 512];
            else if (k < 832)  v = cf[k - 768];
            vals[ch][q] = v;
            amax = fmaxf(amax, fabsf(v));
        }
    }
    #pragma unroll
    for (int o = 16; o; o >>= 1) amax = fmaxf(amax, __shfl_xor_sync(~0u, amax, o));
    float qs = (amax > 0.f) ? ((float)QMAX / amax) : 0.f;
    if (lane == 0) g_sxa[gw] = amax * (1.0f / (float)QMAX);

    size_t base = (size_t)(gw >> 7) * NCH1 * IMG;
    uint32_t off = swz((uint32_t)((gw & 127) * 128 + lane * 4));
    #pragma unroll
    for (int ch = 0; ch < NCH1; ch++) {
        uint32_t ph = 0, pl = 0;
        #pragma unroll
        for (int q = 0; q < 4; q++) {
            int qq = __float2int_rn(vals[ch][q] * qs);
            int qh, ql;
            qsplit(qq, qh, ql);
            ph |= ((uint32_t)(uint8_t)(int8_t)qh) << (q * 8);
            pl |= ((uint32_t)(uint8_t)(int8_t)ql) << (q * 8);
        }
        *reinterpret_cast<uint32_t*>(g_Xt_hi + base + (size_t)ch * IMG + off) = ph;
        *reinterpret_cast<uint32_t*>(g_Xt_lo + base + (size_t)ch * IMG + off) = pl;
    }
}

// ---------------------------------------------------------------------------
// Prep 3: quantize W1 & W2 into split-int8 K-major tile images.
// Warp per output column n (per-column scale over all K).
// ---------------------------------------------------------------------------
__global__ void splitW_kernel(const float* __restrict__ W1, const float* __restrict__ W2) {
    int gw = (blockIdx.x * blockDim.x + threadIdx.x) >> 5;
    int lane = threadIdx.x & 31;
    const float* W; unsigned char *dh, *dl; float* sdst; int K, nch;
    if (gw < HID)            { W = W1; dh = g_W1t_hi; dl = g_W1t_lo; sdst = g_sw1; K = 832;  nch = NCH1; }
    else if (gw < 2 * HID)   { gw -= HID;
                               W = W2; dh = g_W2t_hi; dl = g_W2t_lo; sdst = g_sw2; K = 1024; nch = NCH2; }
    else return;
    int n = gw;

    float amax = 0.f;
    for (int k = lane; k < K; k += 32) amax = fmaxf(amax, fabsf(W[(size_t)k * HID + n]));
    #pragma unroll
    for (int o = 16; o; o >>= 1) amax = fmaxf(amax, __shfl_xor_sync(~0u, amax, o));
    float qs = (amax > 0.f) ? ((float)QMAX / amax) : 0.f;
    if (lane == 0) sdst[n] = amax * (1.0f / (float)QMAX);

    size_t base = (size_t)(n >> 7) * nch * IMG;
    uint32_t off = swz((uint32_t)((n & 127) * 128 + lane * 4));
    for (int ch = 0; ch < nch; ch++) {
        uint32_t ph = 0, pl = 0;
        #pragma unroll
        for (int q = 0; q < 4; q++) {
            int k = ch * 128 + lane * 4 + q;
            float w = (k < K) ? W[(size_t)k * HID + n] : 0.f;
            int qq = __float2int_rn(w * qs);
            int qh, ql;
            qsplit(qq, qh, ql);
            ph |= ((uint32_t)(uint8_t)(int8_t)qh) << (q * 8);
            pl |= ((uint32_t)(uint8_t)(int8_t)ql) << (q * 8);
        }
        *reinterpret_cast<uint32_t*>(dh + base + (size_t)ch * IMG + off) = ph;
        *reinterpret_cast<uint32_t*>(dl + base + (size_t)ch * IMG + off) = pl;
    }
}

// ---------------------------------------------------------------------------
// GEMM: D[128x128] = A[128xK] * B[128xK]^T via int8 split (3 IMMA passes).
// MODE 0: A=Xt, B=W1t -> H tiles (quantized split int8 images)
// MODE 1: A=Ht, B=W2t -> fused bias+relu+W3 dot partials
// Warp grid 2(M) x 4(N); warp tile 64x32.
// ---------------------------------------------------------------------------
template <int MODE>
__global__ __launch_bounds__(THREADS, 1)
void gemm_kernel(const float* __restrict__ bias, const float* __restrict__ W3) {
    constexpr int NCH = MODE ? NCH2 : NCH1;
    extern __shared__ char smem[];
    const uint32_t smem_u = smem_u32(smem);
    const uint32_t stage0 = smem_u + 1024;
    const int tid = threadIdx.x, wid = tid >> 5, lid = tid & 31;
    const int wm = wid >> 2, wn = wid & 3;
    const int g = lid >> 2, t = lid & 3;
    const int mbase = blockIdx.y * M_TILE;

    const unsigned char* At_h = (MODE ? g_Ht_hi : g_Xt_hi) + (size_t)blockIdx.y * NCH * IMG;
    const unsigned char* At_l = (MODE ? g_Ht_lo : g_Xt_lo) + (size_t)blockIdx.y * NCH * IMG;
    const unsigned char* Bt_h = (MODE ? g_W2t_hi : g_W1t_hi) + (size_t)blockIdx.x * NCH * IMG;
    const unsigned char* Bt_l = (MODE ? g_W2t_lo : g_W1t_lo) + (size_t)blockIdx.x * NCH * IMG;
    const float* swc = MODE ? g_sw2 : g_sw1;

    if (tid == 0) {
        MBARRIER_INIT(smem_u, 1); MBARRIER_INIT(smem_u + 8, 1); MBARRIER_INIT(smem_u + 16, 1);
    }
    FENCE_PROXY_ASYNC();
    __syncthreads();

    auto issue = [&](int stg, int kt) {
        if (tid == 0) {
            uint32_t mb = smem_u + stg * 8;
            uint32_t sb = stage0 + stg * STAGE_BYTES;
            MBARRIER_EXPECT_TX(mb, STAGE_BYTES);
            bulk_g2s(sb,           At_h + (size_t)kt * IMG, IMG, mb);
            bulk_g2s(sb + IMG,     At_l + (size_t)kt * IMG, IMG, mb);
            bulk_g2s(sb + 2 * IMG, Bt_h + (size_t)kt * IMG, IMG, mb);
            bulk_g2s(sb + 3 * IMG, Bt_l + (size_t)kt * IMG, IMG, mb);
        }
    };

    int accH[4][4][4], accM[4][4][4];
    #pragma unroll
    for (int i = 0; i < 4; i++)
        #pragma unroll
        for (int j = 0; j < 4; j++)
            #pragma unroll
            for (int q = 0; q < 4; q++) { accH[i][j][q] = 0; accM[i][j][q] = 0; }

    issue(0, 0);
    issue(1, 1);

    const uint32_t arow = (uint32_t)(wm * 64 + (lid & 15));
    const uint32_t aoff = (uint32_t)((lid >> 4) << 4);
    const uint32_t brow = (uint32_t)(wn * 32 + (lid & 7) + ((lid >> 4) << 3));
    const uint32_t boff = (uint32_t)(((lid >> 3) & 1) << 4);

    for (int kt = 0; kt < NCH; kt++) {
        const int stg = kt % 3;
        MBARRIER_WAIT_PARITY(smem_u + stg * 8, (kt / 3) & 1);
        const uint32_t sb = stage0 + stg * STAGE_BYTES;

        #pragma unroll
        for (int s = 0; s < 4; s++) {
            const uint32_t kb = (uint32_t)(s * 32);
            uint32_t Ah[4][4], Av[4][4], Bh[4][2], Bv[4][2];
            #pragma unroll
            for (int i = 0; i < 4; i++) {
                uint32_t ad = sb + swz((arow + i * 16) * 128 + kb + aoff);
                ldsm_x4(Ah[i][0], Ah[i][1], Ah[i][2], Ah[i][3], ad);
                ldsm_x4(Av[i][0], Av[i][1], Av[i][2], Av[i][3], ad + IMG);
            }
            #pragma unroll
            for (int q = 0; q < 2; q++) {
                uint32_t bd = sb + 2 * IMG + swz((brow + q * 16) * 128 + kb + boff);
                ldsm_x4(Bh[2*q][0], Bh[2*q][1], Bh[2*q+1][0], Bh[2*q+1][1], bd);
                ldsm_x4(Bv[2*q][0], Bv[2*q][1], Bv[2*q+1][0], Bv[2*q+1][1], bd + IMG);
            }
            // pass 1: Ah*Bh -> accH
            #pragma unroll
            for (int i = 0; i < 4; i++)
                #pragma unroll
                for (int j = 0; j < 4; j++)
                    imma(accH[i][j], Ah[i][0], Ah[i][1], Ah[i][2], Ah[i][3], Bh[j][0], Bh[j][1]);
            // pass 2: Ah*Bl -> accM
            #pragma unroll
            for (int i = 0; i < 4; i++)
                #pragma unroll
                for (int j = 0; j < 4; j++)
                    imma(accM[i][j], Ah[i][0], Ah[i][1], Ah[i][2], Ah[i][3], Bv[j][0], Bv[j][1]);
            // pass 3: Al*Bh -> accM
            #pragma unroll
            for (int i = 0; i < 4; i++)
                #pragma unroll
                for (int j = 0; j < 4; j++)
                    imma(accM[i][j], Av[i][0], Av[i][1], Av[i][2], Av[i][3], Bh[j][0], Bh[j][1]);
        }
        __syncthreads();
        if (kt + 2 < NCH) issue((kt + 2) % 3, kt + 2);
    }

    // ------------------------------ epilogue ------------------------------
    if (MODE == 0) {
        #pragma unroll
        for (int i = 0; i < 4; i++) {
            int m0 = mbase + wm * 64 + i * 16 + g;
            float sa0 = g_sxa[m0], sa1 = g_sxa[m0 + 8];
            #pragma unroll
            for (int j = 0; j < 4; j++) {
                int n0 = blockIdx.x * N_TILE + wn * 32 + j * 8 + t * 2;
                float s0 = swc[n0], s1 = swc[n0 + 1];
                float bb0 = __ldg(&bias[n0]), bb1 = __ldg(&bias[n0 + 1]);
                #pragma unroll
                for (int h2 = 0; h2 < 2; h2++) {
                    int mrow = m0 + 8 * h2;
                    float sa = h2 ? sa1 : sa0;
                    float f0 = fmaf((float)accH[i][j][2*h2],   16384.f, (float)accM[i][j][2*h2]   * 128.f);
                    float f1 = fmaf((float)accH[i][j][2*h2+1], 16384.f, (float)accM[i][j][2*h2+1] * 128.f);
                    float v0 = fmaxf(fmaf(f0, sa * s0, bb0), 0.f);
                    float v1 = fmaxf(fmaf(f1, sa * s1, bb1), 0.f);
                    int q0 = min(__float2int_rn(v0 * H_QSCALE), QMAX);
                    int q1 = min(__float2int_rn(v1 * H_QSCALE), QMAX);
                    int qh0, ql0, qh1, ql1;
                    qsplit(q0, qh0, ql0);
                    qsplit(q1, qh1, ql1);
                    size_t tb = ((size_t)blockIdx.y * NCH2 + blockIdx.x) * IMG
                              + swz((uint32_t)((mrow & 127) * 128 + (n0 & 127)));
                    uint16_t ph = (uint16_t)((uint8_t)(int8_t)qh0 | ((uint16_t)(uint8_t)(int8_t)qh1 << 8));
                    uint16_t pl = (uint16_t)((uint8_t)(int8_t)ql0 | ((uint16_t)(uint8_t)(int8_t)ql1 << 8));
                    *reinterpret_cast<uint16_t*>(g_Ht_hi + tb) = ph;
                    *reinterpret_cast<uint16_t*>(g_Ht_lo + tb) = pl;
                }
            }
        }
    } else {
        float (*red)[4] = reinterpret_cast<float(*)[4]>(smem + 1024);
        #pragma unroll
        for (int i = 0; i < 4; i++) {
            float d0 = 0.f, d1 = 0.f;
            #pragma unroll
            for (int j = 0; j < 4; j++) {
                int n0 = blockIdx.x * N_TILE + wn * 32 + j * 8 + t * 2;
                float s0 = H_DEQ * swc[n0], s1 = H_DEQ * swc[n0 + 1];
                float bb0 = __ldg(&bias[n0]), bb1 = __ldg(&bias[n0 + 1]);
                float w0 = __ldg(&W3[n0]),   w1 = __ldg(&W3[n0 + 1]);
                float f00 = fmaf((float)accH[i][j][0], 16384.f, (float)accM[i][j][0] * 128.f);
                float f01 = fmaf((float)accH[i][j][1], 16384.f, (float)accM[i][j][1] * 128.f);
                float f10 = fmaf((float)accH[i][j][2], 16384.f, (float)accM[i][j][2] * 128.f);
                float f11 = fmaf((float)accH[i][j][3], 16384.f, (float)accM[i][j][3] * 128.f);
                d0 += fmaxf(fmaf(f00, s0, bb0), 0.f) * w0 + fmaxf(fmaf(f01, s1, bb1), 0.f) * w1;
                d1 += fmaxf(fmaf(f10, s0, bb0), 0.f) * w0 + fmaxf(fmaf(f11, s1, bb1), 0.f) * w1;
            }
            d0 += __shfl_xor_sync(0xffffffffu, d0, 1);
            d0 += __shfl_xor_sync(0xffffffffu, d0, 2);
            d1 += __shfl_xor_sync(0xffffffffu, d1, 1);
            d1 += __shfl_xor_sync(0xffffffffu, d1, 2);
            if (t == 0) {
                red[wm * 64 + i * 16 + g][wn]     = d0;
                red[wm * 64 + i * 16 + g + 8][wn] = d1;
            }
        }
        __syncthreads();
        if (tid < M_TILE) {
            float s = red[tid][0] + red[tid][1] + red[tid][2] + red[tid][3];
            g_part[(size_t)blockIdx.x * N_CAND + mbase + tid] = s;
        }
    }
}

// ---------------------------------------------------------------------------
// Final reduce: out[m] = b3 + sum over 8 n-tile partials (deterministic)
// ---------------------------------------------------------------------------
__global__ void reduce_kernel(const float* __restrict__ b3, float* __restrict__ out) {
    int m = blockIdx.x * blockDim.x + threadIdx.x;
    if (m < N_CAND) {
        float s = b3[0];
        #pragma unroll
        for (int tt = 0; tt < N_NT; tt++) s += g_part[(size_t)tt * N_CAND + m];
        out[m] = s;
    }
}

// ---------------------------------------------------------------------------
// Launch
// ---------------------------------------------------------------------------
extern "C" void kernel_launch(void* const* d_in, const int* in_sizes, int n_in,
                              void* d_out, int out_size) {
    const float* pf   = (const float*)d_in[0];   // (256,19,19)
    const float* cand = (const float*)d_in[1];   // (65536,64)
    const float* W1   = (const float*)d_in[2];   // (832,1024)
    const float* b1   = (const float*)d_in[3];
    const float* W2   = (const float*)d_in[4];   // (1024,1024)
    const float* b2   = (const float*)d_in[5];
    const float* W3   = (const float*)d_in[6];   // (1024,1)
    const float* b3   = (const float*)d_in[7];
    float* out = (float*)d_out;
    (void)in_sizes; (void)n_in; (void)out_size;

    (void)cudaFuncSetAttribute(gemm_kernel<0>,
                               cudaFuncAttributeMaxDynamicSharedMemorySize, SMEM_TOTAL);
    (void)cudaFuncSetAttribute(gemm_kernel<1>,
                               cudaFuncAttributeMaxDynamicSharedMemorySize, SMEM_TOTAL);

    prep_pf_kernel<<<BOARD_SQ + 1, 256>>>(pf);
    buildX_kernel<<<N_CAND / 8, 256>>>(cand);
    splitW_kernel<<<(2 * HID * 32) / 256, 256>>>(W1, W2);

    dim3 grid(N_NT, N_CAND / M_TILE);            // (8, 512)
    gemm_kernel<0><<<grid, THREADS, SMEM_TOTAL>>>(b1, nullptr);
    gemm_kernel<1><<<grid, THREADS, SMEM_TOTAL>>>(b2, W3);

    reduce_kernel<<<(N_CAND + 255) / 256, 256>>>(b3, out);
}

// round 11
// speedup vs baseline: 3.8359x; 3.8359x over previous
#include <cuda_runtime.h>
#include <cuda_bf16.h>
#include <cstdint>

// ============================================================================
// CandidateScorer — structure-exploiting split-bf16 mma.sync pipeline.
//   scores = relu(relu(X W1 + b1) W2 + b2) W3 + b3
// Layer 1 decomposition (X = [go|to|gpool|cand]):
//   H1[i] = relu( P_go[go_i] + P_to[to_i] + gvec + cand_i · W1c )
//   where P_* = pf_t · W1-block (361x1024, fp32 exact), gvec = b1 + gp·W1_gp,
//   and the cand part is a K=64 split-bf16 tensor GEMM (3 passes).
// Layer 2: R7-proven 3-pass split-bf16 GEMM (Ah*Bh + Ah*Bl + Al*Bh) with
//   cp.async.bulk staging of pre-swizzled gmem tile images; bias+relu+W3 dot
//   fused into the epilogue (H2 never materialized). Deterministic reduce.
// (int8 IMMA abandoned: legacy s8 mma.sync is ~8x slower/instr on sm_103a.)
// ============================================================================

#define N_CAND 65536
#define HID    1024
#define BOARD_SQ 361

#define M_TILE 128
#define N_TILE 256
#define KCH    64               // 64 bf16 = 128 B per row (swizzle atom)
#define THREADS 256
#define NCH2   16               // 1024 / 64
#define N_MT   (N_CAND / M_TILE)  // 512
#define N_NT   (HID / N_TILE)     // 4

#define A_IMG  16384            // 128 rows * 128 B
#define B_IMG  32768            // 256 rows * 128 B
#define STAGE_BYTES (2 * A_IMG + 2 * B_IMG)          // 98304
#define SMEM_TOTAL  (1024 + 2 * STAGE_BYTES)         // 197632

// ---------------------------------------------------------------------------
// Scratch (allocation-free rule: __device__ globals)
// ---------------------------------------------------------------------------
__device__ __align__(1024) unsigned char g_Xc_hi[(size_t)N_MT * A_IMG];   // cand K=64 images
__device__ __align__(1024) unsigned char g_Xc_lo[(size_t)N_MT * A_IMG];
__device__ __align__(1024) unsigned char g_W1c_hi[(size_t)N_NT * B_IMG];
__device__ __align__(1024) unsigned char g_W1c_lo[(size_t)N_NT * B_IMG];
__device__ __align__(1024) unsigned char g_W2t_hi[(size_t)N_NT * NCH2 * B_IMG];
__device__ __align__(1024) unsigned char g_W2t_lo[(size_t)N_NT * NCH2 * B_IMG];
__device__ __align__(1024) unsigned char g_Ht_hi[(size_t)N_MT * NCH2 * A_IMG];
__device__ __align__(1024) unsigned char g_Ht_lo[(size_t)N_MT * NCH2 * A_IMG];
__device__ float g_pf_t[BOARD_SQ * 256];         // transposed feat map [p][c]
__device__ float g_gpool[256];
__device__ float g_P[(size_t)768 * HID];         // rows 0..360 go, 384..744 to
__device__ float g_gvec[HID];                    // b1 + gp . W1[512:768]
__device__ int   g_go[N_CAND];
__device__ int   g_to[N_CAND];
__device__ float g_part[(size_t)N_NT * N_CAND];

// ---------------------------------------------------------------------------
// PTX helpers (plain-target: cp.async.bulk / mbarrier / ldmatrix / mma.sync)
// ---------------------------------------------------------------------------
__device__ __forceinline__ uint32_t smem_u32(const void* p) {
    uint32_t a;
    asm("{ .reg .u64 t; cvta.to.shared.u64 t, %1; cvt.u32.u64 %0, t; }" : "=r"(a) : "l"(p));
    return a;
}

#define MBARRIER_INIT(mbar, cnt) \
    asm volatile("mbarrier.init.shared.b64 [%0], %1;" \
                 :: "r"((uint32_t)(mbar)), "r"((uint32_t)(cnt)) : "memory")
#define MBARRIER_EXPECT_TX(mbar, bytes) \
    asm volatile("mbarrier.arrive.expect_tx.shared.b64 _, [%0], %1;" \
                 :: "r"((uint32_t)(mbar)), "r"((uint32_t)(bytes)) : "memory")
#define FENCE_PROXY_ASYNC() \
    asm volatile("fence.proxy.async.shared::cta;" ::: "memory")

__device__ __forceinline__ void bulk_g2s(uint32_t dst, const void* src,
                                         uint32_t bytes, uint32_t mbar) {
    asm volatile(
        "cp.async.bulk.shared::cluster.global.mbarrier::complete_tx::bytes "
        "[%0], [%1], %2, [%3];"
        :: "r"(dst), "l"(__cvta_generic_to_global(src)), "r"(bytes), "r"(mbar)
        : "memory");
}

#define MBARRIER_WAIT_PARITY(mbar_smem_addr, phase_parity) do { \
    uint32_t _mbar = (uint32_t)(mbar_smem_addr); \
    uint32_t _parity = (uint32_t)(phase_parity); \
    uint32_t _done; \
    asm volatile( \
        "{\n\t.reg .pred p;\n\t" \
        "mbarrier.try_wait.parity.acquire.cta.shared::cta.b64 p, [%1], %2;\n\t" \
        "selp.b32 %0, 1, 0, p;\n\t}" \
        : "=r"(_done) : "r"(_mbar), "r"(_parity) : "memory"); \
    if (!_done) { \
        asm volatile( \
            "{\n\t.reg .pred P1;\n\t" \
            "WAIT_LOOP_%=:\n\t" \
            "mbarrier.try_wait.parity.acquire.cta.shared::cta.b64 P1, [%0], %1, 0x989680;\n\t" \
            "@P1 bra.uni WAIT_DONE_%=;\n\t" \
            "bra.uni WAIT_LOOP_%=;\n\t" \
            "WAIT_DONE_%=:\n\t}" \
            :: "r"(_mbar), "r"(_parity) : "memory"); \
    } \
} while (0)

__device__ __forceinline__ void ldsm_x4(uint32_t& r0, uint32_t& r1, uint32_t& r2,
                                        uint32_t& r3, uint32_t addr) {
    asm volatile("ldmatrix.sync.aligned.m8n8.x4.shared.b16 {%0,%1,%2,%3}, [%4];"
                 : "=r"(r0), "=r"(r1), "=r"(r2), "=r"(r3) : "r"(addr));
}

__device__ __forceinline__ void mma_bf16(float* c, uint32_t a0, uint32_t a1,
                                         uint32_t a2, uint32_t a3,
                                         uint32_t b0, uint32_t b1) {
    asm volatile(
        "mma.sync.aligned.m16n8k16.row.col.f32.bf16.bf16.f32 "
        "{%0,%1,%2,%3}, {%4,%5,%6,%7}, {%8,%9}, {%0,%1,%2,%3};"
        : "+f"(c[0]), "+f"(c[1]), "+f"(c[2]), "+f"(c[3])
        : "r"(a0), "r"(a1), "r"(a2), "r"(a3), "r"(b0), "r"(b1));
}

__device__ __forceinline__ uint32_t swz(uint32_t off) {      // SW128 pattern
    return off ^ ((off >> 3) & 0x70);
}

__device__ __forceinline__ uint32_t pack_hi(float v0, float v1, float& r0, float& r1) {
    __nv_bfloat162 hp;
    hp.x = __float2bfloat16(v0);
    hp.y = __float2bfloat16(v1);
    r0 = v0 - __bfloat162float(hp.x);
    r1 = v1 - __bfloat162float(hp.y);
    return *reinterpret_cast<uint32_t*>(&hp);
}
__device__ __forceinline__ uint32_t pack_lo(float r0, float r1) {
    __nv_bfloat162 lp;
    lp.x = __float2bfloat16(r0);
    lp.y = __float2bfloat16(r1);
    return *reinterpret_cast<uint32_t*>(&lp);
}

// ---------------------------------------------------------------------------
// Prep 1: transpose policy map + global pool
// ---------------------------------------------------------------------------
__global__ void prep_pf_kernel(const float* __restrict__ pf) {
    int b = blockIdx.x, t = threadIdx.x;
    if (b < BOARD_SQ) {
        g_pf_t[b * 256 + t] = pf[(size_t)t * BOARD_SQ + b];   // pf_t[p][c]
    } else {                                                  // b == BOARD_SQ
        const float* p = pf + (size_t)t * BOARD_SQ;
        float s = 0.f;
        for (int i = 0; i < BOARD_SQ; i++) s += p[i];
        g_gpool[t] = s * (1.0f / 361.0f);
    }
}

// ---------------------------------------------------------------------------
// Prep 2: decode go/to indices + build cand X (K=64) split-bf16 tile images.
// One warp per candidate (lane covers 2 of the 64 features).
// ---------------------------------------------------------------------------
__global__ void decode_buildXc_kernel(const float* __restrict__ cand) {
    int gw = (blockIdx.x * blockDim.x + threadIdx.x) >> 5;
    int lane = threadIdx.x & 31;
    if (gw >= N_CAND) return;
    const float* cf = cand + (size_t)gw * 64;
    if (lane == 0) {
        int gr = min(max((int)(cf[5] * 18.0f), 0), 18);
        int gc = min(max((int)(cf[6] * 18.0f), 0), 18);
        int tr = min(max((int)(cf[7] * 18.0f), 0), 18);
        int tc = min(max((int)(cf[8] * 18.0f), 0), 18);
        g_go[gw] = gr * 19 + gc;
        g_to[gw] = tr * 19 + tc;
    }
    float v0 = cf[lane * 2], v1 = cf[lane * 2 + 1];
    float r0, r1;
    uint32_t hp = pack_hi(v0, v1, r0, r1);
    uint32_t lp = pack_lo(r0, r1);
    size_t tb = (size_t)(gw >> 7) * A_IMG + swz((uint32_t)((gw & 127) * 128 + lane * 4));
    *reinterpret_cast<uint32_t*>(g_Xc_hi + tb) = hp;
    *reinterpret_cast<uint32_t*>(g_Xc_lo + tb) = lp;
}

// ---------------------------------------------------------------------------
// Prep 3: split W1c (rows 768..831) and W2 into K-major split-bf16 images.
// ---------------------------------------------------------------------------
__global__ void splitW_kernel(const float* __restrict__ W1, const float* __restrict__ W2) {
    int gw = (blockIdx.x * blockDim.x + threadIdx.x) >> 5;
    int lane = threadIdx.x & 31;
    if (gw < HID) {                       // W1c: warp per output column n
        int n = gw;
        int k = lane * 2;
        float w0 = W1[(size_t)(768 + k) * HID + n];
        float w1 = W1[(size_t)(769 + k) * HID + n];
        float r0, r1;
        uint32_t hp = pack_hi(w0, w1, r0, r1);
        uint32_t lp = pack_lo(r0, r1);
        size_t tb = (size_t)(n >> 8) * B_IMG + swz((uint32_t)((n & 255) * 128 + lane * 4));
        *reinterpret_cast<uint32_t*>(g_W1c_hi + tb) = hp;
        *reinterpret_cast<uint32_t*>(g_W1c_lo + tb) = lp;
    } else if (gw < 2 * HID) {            // W2: warp per column n, 16 chunks
        int n = gw - HID;
        size_t base = (size_t)(n >> 8) * NCH2 * B_IMG;
        uint32_t off = swz((uint32_t)((n & 255) * 128 + lane * 4));
        #pragma unroll
        for (int ch = 0; ch < NCH2; ch++) {
            int k0 = ch * KCH + lane * 2;
            float w0 = W2[(size_t)k0 * HID + n];
            float w1 = W2[(size_t)(k0 + 1) * HID + n];
            float r0, r1;
            uint32_t hp = pack_hi(w0, w1, r0, r1);
            uint32_t lp = pack_lo(r0, r1);
            *reinterpret_cast<uint32_t*>(g_W2t_hi + base + (size_t)ch * B_IMG + off) = hp;
            *reinterpret_cast<uint32_t*>(g_W2t_lo + base + (size_t)ch * B_IMG + off) = lp;
        }
    }
}

// ---------------------------------------------------------------------------
// Prep 4: P tables (fp32, exact).  grid (97, 4), block 256.
//   gx 0..47:  go rows  P[p]      = pf_t[p]   . W1[0:256]
//   gx 48..95: to rows  P[384+p]  = pf_t[p]   . W1[256:512]
//   gx 96:     gvec     = b1 + gp . W1[512:768]
// ---------------------------------------------------------------------------
__global__ void pgemm_kernel(const float* __restrict__ W1, const float* __restrict__ b1) {
    int n = blockIdx.y * 256 + threadIdx.x;
    int gx = blockIdx.x;
    if (gx == 96) {
        float s = b1[n];
        for (int c = 0; c < 256; c++)
            s = fmaf(g_gpool[c], W1[(size_t)(512 + c) * HID + n], s);
        g_gvec[n] = s;
        return;
    }
    int isto = gx >= 48;
    int r0 = (isto ? gx - 48 : gx) * 8;
    const float* Wb = W1 + (size_t)(isto ? 256 : 0) * HID;
    const float* pfr[8];
    #pragma unroll
    for (int rr = 0; rr < 8; rr++) pfr[rr] = g_pf_t + (size_t)min(r0 + rr, 360) * 256;
    float acc[8] = {0, 0, 0, 0, 0, 0, 0, 0};
    for (int c = 0; c < 256; c++) {
        float w = Wb[(size_t)c * HID + n];
        #pragma unroll
        for (int rr = 0; rr < 8; rr++) acc[rr] = fmaf(pfr[rr][c], w, acc[rr]);
    }
    #pragma unroll
    for (int rr = 0; rr < 8; rr++) {
        int p = r0 + rr;
        if (p < BOARD_SQ) g_P[(size_t)(isto ? 384 + p : p) * HID + n] = acc[rr];
    }
}

// ---------------------------------------------------------------------------
// GEMM: D[128x256] = A[128xK] * B[256xK]^T, 3-pass split bf16, bulk staging.
// MODE 0: A=Xc (K=64), B=W1c; epilogue adds P_go/P_to/gvec, relu -> H images
// MODE 1: A=Ht (K=1024), B=W2t; epilogue bias+relu+W3 dot partials
// ---------------------------------------------------------------------------
template <int MODE>
__global__ __launch_bounds__(THREADS, 1)
void gemm_kernel(const float* __restrict__ bias, const float* __restrict__ W3) {
    constexpr int NCH = MODE ? NCH2 : 1;
    extern __shared__ char smem[];
    const uint32_t smem_u = smem_u32(smem);
    const uint32_t stage0 = smem_u + 1024;
    const int tid = threadIdx.x;
    const int wid = tid >> 5, lid = tid & 31;
    const int wm = wid >> 2, wn = wid & 3;          // warp grid 2(M) x 4(N)
    const int nbase = blockIdx.x * N_TILE;
    const int mbase = blockIdx.y * M_TILE;
    const int g = lid >> 2, t = lid & 3;

    const unsigned char* At_h = MODE ? g_Ht_hi + (size_t)blockIdx.y * NCH2 * A_IMG
                                     : g_Xc_hi + (size_t)blockIdx.y * A_IMG;
    const unsigned char* At_l = MODE ? g_Ht_lo + (size_t)blockIdx.y * NCH2 * A_IMG
                                     : g_Xc_lo + (size_t)blockIdx.y * A_IMG;
    const unsigned char* Bt_h = MODE ? g_W2t_hi + (size_t)blockIdx.x * NCH2 * B_IMG
                                     : g_W1c_hi + (size_t)blockIdx.x * B_IMG;
    const unsigned char* Bt_l = MODE ? g_W2t_lo + (size_t)blockIdx.x * NCH2 * B_IMG
                                     : g_W1c_lo + (size_t)blockIdx.x * B_IMG;

    if (tid == 0) { MBARRIER_INIT(smem_u, 1); MBARRIER_INIT(smem_u + 8, 1); }
    FENCE_PROXY_ASYNC();
    __syncthreads();

    auto issue = [&](int stg, int kt) {
        if (tid == 0) {
            uint32_t mb = smem_u + stg * 8;
            uint32_t sb = stage0 + stg * STAGE_BYTES;
            MBARRIER_EXPECT_TX(mb, STAGE_BYTES);
            bulk_g2s(sb,             At_h + (size_t)kt * A_IMG, A_IMG, mb);
            bulk_g2s(sb + A_IMG,     At_l + (size_t)kt * A_IMG, A_IMG, mb);
            bulk_g2s(sb + 2 * A_IMG, Bt_h + (size_t)kt * B_IMG, B_IMG, mb);
            bulk_g2s(sb + 2 * A_IMG + B_IMG, Bt_l + (size_t)kt * B_IMG, B_IMG, mb);
        }
    };

    float acc[4][8][4];
    #pragma unroll
    for (int i = 0; i < 4; i++)
        #pragma unroll
        for (int j = 0; j < 8; j++)
            #pragma unroll
            for (int q = 0; q < 4; q++) acc[i][j][q] = 0.f;

    issue(0, 0);

    const int rlo = lid & 15;
    const uint32_t khalf16 = (uint32_t)((lid >> 4) * 16);

    for (int kt = 0; kt < NCH; kt++) {
        if (kt + 1 < NCH) issue((kt + 1) & 1, kt + 1);
        MBARRIER_WAIT_PARITY(smem_u + (kt & 1) * 8, (kt >> 1) & 1);

        const uint32_t sb = stage0 + (kt & 1) * STAGE_BYTES;
        #pragma unroll
        for (int s = 0; s < 4; s++) {
            const uint32_t kb = (uint32_t)(s * 32) + khalf16;
            uint32_t Af[4][4], Bx[4][4], By[4][4];
            #pragma unroll
            for (int i = 0; i < 4; i++) {            // A-hi frags
                uint32_t a = sb + swz((uint32_t)((wm * 64 + i * 16 + rlo) * 128) + kb);
                ldsm_x4(Af[i][0], Af[i][1], Af[i][2], Af[i][3], a);
            }
            #pragma unroll
            for (int jj = 0; jj < 4; jj++) {         // B-hi / B-lo frags
                uint32_t ro = swz((uint32_t)((wn * 64 + jj * 16 + rlo) * 128) + kb);
                ldsm_x4(Bx[jj][0], Bx[jj][1], Bx[jj][2], Bx[jj][3],
                        sb + 2 * A_IMG + ro);
                ldsm_x4(By[jj][0], By[jj][1], By[jj][2], By[jj][3],
                        sb + 2 * A_IMG + B_IMG + ro);
            }
            // pass 1: Ah*Bh, pass 2: Ah*Bl
            #pragma unroll
            for (int i = 0; i < 4; i++)
                #pragma unroll
                for (int jj = 0; jj < 4; jj++) {
                    mma_bf16(acc[i][2*jj],   Af[i][0],Af[i][1],Af[i][2],Af[i][3], Bx[jj][0], Bx[jj][2]);
                    mma_bf16(acc[i][2*jj+1], Af[i][0],Af[i][1],Af[i][2],Af[i][3], Bx[jj][1], Bx[jj][3]);
                    mma_bf16(acc[i][2*jj],   Af[i][0],Af[i][1],Af[i][2],Af[i][3], By[jj][0], By[jj][2]);
                    mma_bf16(acc[i][2*jj+1], Af[i][0],Af[i][1],Af[i][2],Af[i][3], By[jj][1], By[jj][3]);
                }
            // pass 3: Al*Bh (reuse Af regs)
            #pragma unroll
            for (int i = 0; i < 4; i++) {
                uint32_t a = sb + A_IMG + swz((uint32_t)((wm * 64 + i * 16 + rlo) * 128) + kb);
                ldsm_x4(Af[i][0], Af[i][1], Af[i][2], Af[i][3], a);
            }
            #pragma unroll
            for (int i = 0; i < 4; i++)
                #pragma unroll
                for (int jj = 0; jj < 4; jj++) {
                    mma_bf16(acc[i][2*jj],   Af[i][0],Af[i][1],Af[i][2],Af[i][3], Bx[jj][0], Bx[jj][2]);
                    mma_bf16(acc[i][2*jj+1], Af[i][0],Af[i][1],Af[i][2],Af[i][3], Bx[jj][1], Bx[jj][3]);
                }
        }
        __syncthreads();
    }

    // ------------------------------ epilogue ------------------------------
    if (MODE == 0) {
        #pragma unroll
        for (int i = 0; i < 4; i++) {
            #pragma unroll
            for (int h2 = 0; h2 < 2; h2++) {
                int m0 = mbase + wm * 64 + i * 16 + g + 8 * h2;
                const float* Pg = g_P + (size_t)g_go[m0] * HID;
                const float* Pt = g_P + (size_t)(384 + g_to[m0]) * HID;
                #pragma unroll
                for (int j = 0; j < 8; j++) {
                    int n0 = nbase + wn * 64 + j * 8 + 2 * t;
                    float v0 = acc[i][j][2*h2]     + Pg[n0]     + Pt[n0]     + g_gvec[n0];
                    float v1 = acc[i][j][2*h2 + 1] + Pg[n0 + 1] + Pt[n0 + 1] + g_gvec[n0 + 1];
                    v0 = fmaxf(v0, 0.f); v1 = fmaxf(v1, 0.f);
                    float r0, r1;
                    uint32_t hp = pack_hi(v0, v1, r0, r1);
                    uint32_t lp = pack_lo(r0, r1);
                    size_t tb = ((size_t)(m0 >> 7) * NCH2 + (n0 >> 6)) * A_IMG
                              + swz((uint32_t)((m0 & 127) * 128 + (n0 & 63) * 2));
                    *reinterpret_cast<uint32_t*>(g_Ht_hi + tb) = hp;
                    *reinterpret_cast<uint32_t*>(g_Ht_lo + tb) = lp;
                }
            }
        }
    } else {
        __syncthreads();                       // stages dead; overlay reducer
        float (*red)[4] = reinterpret_cast<float(*)[4]>(smem + 1024);
        #pragma unroll
        for (int i = 0; i < 4; i++) {
            float d0 = 0.f, d1 = 0.f;
            #pragma unroll
            for (int j = 0; j < 8; j++) {
                int n0 = nbase + wn * 64 + j * 8 + 2 * t;
                float bb0 = __ldg(&bias[n0]), bb1 = __ldg(&bias[n0 + 1]);
                float w0 = __ldg(&W3[n0]),   w1 = __ldg(&W3[n0 + 1]);
                d0 += fmaxf(acc[i][j][0] + bb0, 0.f) * w0 + fmaxf(acc[i][j][1] + bb1, 0.f) * w1;
                d1 += fmaxf(acc[i][j][2] + bb0, 0.f) * w0 + fmaxf(acc[i][j][3] + bb1, 0.f) * w1;
            }
            d0 += __shfl_xor_sync(0xffffffffu, d0, 1);
            d0 += __shfl_xor_sync(0xffffffffu, d0, 2);
            d1 += __shfl_xor_sync(0xffffffffu, d1, 1);
            d1 += __shfl_xor_sync(0xffffffffu, d1, 2);
            if (t == 0) {
                red[wm * 64 + i * 16 + g][wn]     = d0;
                red[wm * 64 + i * 16 + g + 8][wn] = d1;
            }
        }
        __syncthreads();
        if (tid < M_TILE) {
            float s = red[tid][0] + red[tid][1] + red[tid][2] + red[tid][3];
            g_part[(size_t)blockIdx.x * N_CAND + mbase + tid] = s;
        }
    }
}

// ---------------------------------------------------------------------------
// Final reduce: out[m] = b3 + sum over 4 n-tile partials (deterministic)
// ---------------------------------------------------------------------------
__global__ void reduce_kernel(const float* __restrict__ b3, float* __restrict__ out) {
    int m = blockIdx.x * blockDim.x + threadIdx.x;
    if (m < N_CAND) {
        float s = b3[0];
        #pragma unroll
        for (int tt = 0; tt < N_NT; tt++) s += g_part[(size_t)tt * N_CAND + m];
        out[m] = s;
    }
}

// ---------------------------------------------------------------------------
// Launch
// ---------------------------------------------------------------------------
extern "C" void kernel_launch(void* const* d_in, const int* in_sizes, int n_in,
                              void* d_out, int out_size) {
    const float* pf   = (const float*)d_in[0];   // (256,19,19)
    const float* cand = (const float*)d_in[1];   // (65536,64)
    const float* W1   = (const float*)d_in[2];   // (832,1024)
    const float* b1   = (const float*)d_in[3];
    const float* W2   = (const float*)d_in[4];   // (1024,1024)
    const float* b2   = (const float*)d_in[5];
    const float* W3   = (const float*)d_in[6];   // (1024,1)
    const float* b3   = (const float*)d_in[7];
    float* out = (float*)d_out;
    (void)in_sizes; (void)n_in; (void)out_size;

    (void)cudaFuncSetAttribute(gemm_kernel<0>,
                               cudaFuncAttributeMaxDynamicSharedMemorySize, SMEM_TOTAL);
    (void)cudaFuncSetAttribute(gemm_kernel<1>,
                               cudaFuncAttributeMaxDynamicSharedMemorySize, SMEM_TOTAL);

    prep_pf_kernel<<<BOARD_SQ + 1, 256>>>(pf);
    decode_buildXc_kernel<<<N_CAND / 8, 256>>>(cand);
    splitW_kernel<<<(2 * HID * 32) / 256, 256>>>(W1, W2);
    pgemm_kernel<<<dim3(97, 4), 256>>>(W1, b1);

    dim3 grid(N_NT, N_CAND / M_TILE);            // (4, 512)
    gemm_kernel<0><<<grid, THREADS, SMEM_TOTAL>>>(b1, nullptr);   // layer 1 (cand GEMM + gather)
    gemm_kernel<1><<<grid, THREADS, SMEM_TOTAL>>>(b2, W3);        // layer 2 + fused W3

    reduce_kernel<<<(N_CAND + 255) / 256, 256>>>(b3, out);
}

// round 15
// speedup vs baseline: 4.2438x; 1.1063x over previous
#include <cuda_runtime.h>
#include <cuda_bf16.h>
#include <cstdint>

// ============================================================================
// CandidateScorer — structure-exploiting split-bf16 mma.sync pipeline.
//   scores = relu(relu(X W1 + b1) W2 + b2) W3 + b3
// Layer 1 decomposition (X = [go|to|gpool|cand]):
//   H1[i] = relu( P_go[go_i] + P_to[to_i] + gvec + cand_i · W1c )
//   where P_* = pf_t · W1-block (361x1024, fp32 exact), gvec = b1 + gp·W1_gp,
//   and the cand part is a K=64 split-bf16 tensor GEMM (3 passes).
// Layer 2: 3-pass split-bf16 GEMM (Ah*Bh + Ah*Bl + Al*Bh) with cp.async.bulk
//   staging of pre-swizzled gmem tile images; bias+relu+W3 dot fused into the
//   epilogue (H2 never materialized). Deterministic reduce.
// R11: 16 warps/CTA (4 per SMSP) to keep the HMMA pipe fed; pgemm unrolled
//   x4 for MLP.
// ============================================================================

#define N_CAND 65536
#define HID    1024
#define BOARD_SQ 361

#define M_TILE 128
#define N_TILE 256
#define KCH    64               // 64 bf16 = 128 B per row (swizzle atom)
#define THREADS 512
#define NCH2   16               // 1024 / 64
#define N_MT   (N_CAND / M_TILE)  // 512
#define N_NT   (HID / N_TILE)     // 4

#define A_IMG  16384            // 128 rows * 128 B
#define B_IMG  32768            // 256 rows * 128 B
#define STAGE_BYTES (2 * A_IMG + 2 * B_IMG)          // 98304
#define SMEM_TOTAL  (1024 + 2 * STAGE_BYTES)         // 197632

// ---------------------------------------------------------------------------
// Scratch (allocation-free rule: __device__ globals)
// ---------------------------------------------------------------------------
__device__ __align__(1024) unsigned char g_Xc_hi[(size_t)N_MT * A_IMG];   // cand K=64 images
__device__ __align__(1024) unsigned char g_Xc_lo[(size_t)N_MT * A_IMG];
__device__ __align__(1024) unsigned char g_W1c_hi[(size_t)N_NT * B_IMG];
__device__ __align__(1024) unsigned char g_W1c_lo[(size_t)N_NT * B_IMG];
__device__ __align__(1024) unsigned char g_W2t_hi[(size_t)N_NT * NCH2 * B_IMG];
__device__ __align__(1024) unsigned char g_W2t_lo[(size_t)N_NT * NCH2 * B_IMG];
__device__ __align__(1024) unsigned char g_Ht_hi[(size_t)N_MT * NCH2 * A_IMG];
__device__ __align__(1024) unsigned char g_Ht_lo[(size_t)N_MT * NCH2 * A_IMG];
__device__ float g_pf_t[BOARD_SQ * 256];         // transposed feat map [p][c]
__device__ float g_gpool[256];
__device__ float g_P[(size_t)768 * HID];         // rows 0..360 go, 384..744 to
__device__ float g_gvec[HID];                    // b1 + gp . W1[512:768]
__device__ int   g_go[N_CAND];
__device__ int   g_to[N_CAND];
__device__ float g_part[(size_t)N_NT * N_CAND];

// ---------------------------------------------------------------------------
// PTX helpers (plain-target: cp.async.bulk / mbarrier / ldmatrix / mma.sync)
// ---------------------------------------------------------------------------
__device__ __forceinline__ uint32_t smem_u32(const void* p) {
    uint32_t a;
    asm("{ .reg .u64 t; cvta.to.shared.u64 t, %1; cvt.u32.u64 %0, t; }" : "=r"(a) : "l"(p));
    return a;
}

#define MBARRIER_INIT(mbar, cnt) \
    asm volatile("mbarrier.init.shared.b64 [%0], %1;" \
                 :: "r"((uint32_t)(mbar)), "r"((uint32_t)(cnt)) : "memory")
#define MBARRIER_EXPECT_TX(mbar, bytes) \
    asm volatile("mbarrier.arrive.expect_tx.shared.b64 _, [%0], %1;" \
                 :: "r"((uint32_t)(mbar)), "r"((uint32_t)(bytes)) : "memory")
#define FENCE_PROXY_ASYNC() \
    asm volatile("fence.proxy.async.shared::cta;" ::: "memory")

__device__ __forceinline__ void bulk_g2s(uint32_t dst, const void* src,
                                         uint32_t bytes, uint32_t mbar) {
    asm volatile(
        "cp.async.bulk.shared::cluster.global.mbarrier::complete_tx::bytes "
        "[%0], [%1], %2, [%3];"
        :: "r"(dst), "l"(__cvta_generic_to_global(src)), "r"(bytes), "r"(mbar)
        : "memory");
}

#define MBARRIER_WAIT_PARITY(mbar_smem_addr, phase_parity) do { \
    uint32_t _mbar = (uint32_t)(mbar_smem_addr); \
    uint32_t _parity = (uint32_t)(phase_parity); \
    uint32_t _done; \
    asm volatile( \
        "{\n\t.reg .pred p;\n\t" \
        "mbarrier.try_wait.parity.acquire.cta.shared::cta.b64 p, [%1], %2;\n\t" \
        "selp.b32 %0, 1, 0, p;\n\t}" \
        : "=r"(_done) : "r"(_mbar), "r"(_parity) : "memory"); \
    if (!_done) { \
        asm volatile( \
            "{\n\t.reg .pred P1;\n\t" \
            "WAIT_LOOP_%=:\n\t" \
            "mbarrier.try_wait.parity.acquire.cta.shared::cta.b64 P1, [%0], %1, 0x989680;\n\t" \
            "@P1 bra.uni WAIT_DONE_%=;\n\t" \
            "bra.uni WAIT_LOOP_%=;\n\t" \
            "WAIT_DONE_%=:\n\t}" \
            :: "r"(_mbar), "r"(_parity) : "memory"); \
    } \
} while (0)

__device__ __forceinline__ void ldsm_x4(uint32_t& r0, uint32_t& r1, uint32_t& r2,
                                        uint32_t& r3, uint32_t addr) {
    asm volatile("ldmatrix.sync.aligned.m8n8.x4.shared.b16 {%0,%1,%2,%3}, [%4];"
                 : "=r"(r0), "=r"(r1), "=r"(r2), "=r"(r3) : "r"(addr));
}

__device__ __forceinline__ void mma_bf16(float* c, uint32_t a0, uint32_t a1,
                                         uint32_t a2, uint32_t a3,
                                         uint32_t b0, uint32_t b1) {
    asm volatile(
        "mma.sync.aligned.m16n8k16.row.col.f32.bf16.bf16.f32 "
        "{%0,%1,%2,%3}, {%4,%5,%6,%7}, {%8,%9}, {%0,%1,%2,%3};"
        : "+f"(c[0]), "+f"(c[1]), "+f"(c[2]), "+f"(c[3])
        : "r"(a0), "r"(a1), "r"(a2), "r"(a3), "r"(b0), "r"(b1));
}

__device__ __forceinline__ uint32_t swz(uint32_t off) {      // SW128 pattern
    return off ^ ((off >> 3) & 0x70);
}

__device__ __forceinline__ uint32_t pack_hi(float v0, float v1, float& r0, float& r1) {
    __nv_bfloat162 hp;
    hp.x = __float2bfloat16(v0);
    hp.y = __float2bfloat16(v1);
    r0 = v0 - __bfloat162float(hp.x);
    r1 = v1 - __bfloat162float(hp.y);
    return *reinterpret_cast<uint32_t*>(&hp);
}
__device__ __forceinline__ uint32_t pack_lo(float r0, float r1) {
    __nv_bfloat162 lp;
    lp.x = __float2bfloat16(r0);
    lp.y = __float2bfloat16(r1);
    return *reinterpret_cast<uint32_t*>(&lp);
}

// ---------------------------------------------------------------------------
// Prep 1: transpose policy map + global pool
// ---------------------------------------------------------------------------
__global__ void prep_pf_kernel(const float* __restrict__ pf) {
    int b = blockIdx.x, t = threadIdx.x;
    if (b < BOARD_SQ) {
        g_pf_t[b * 256 + t] = pf[(size_t)t * BOARD_SQ + b];   // pf_t[p][c]
    } else {                                                  // b == BOARD_SQ
        const float* p = pf + (size_t)t * BOARD_SQ;
        float s = 0.f;
        for (int i = 0; i < BOARD_SQ; i++) s += p[i];
        g_gpool[t] = s * (1.0f / 361.0f);
    }
}

// ---------------------------------------------------------------------------
// Prep 2: decode go/to indices + build cand X (K=64) split-bf16 tile images.
// ---------------------------------------------------------------------------
__global__ void decode_buildXc_kernel(const float* __restrict__ cand) {
    int gw = (blockIdx.x * blockDim.x + threadIdx.x) >> 5;
    int lane = threadIdx.x & 31;
    if (gw >= N_CAND) return;
    const float* cf = cand + (size_t)gw * 64;
    if (lane == 0) {
        int gr = min(max((int)(cf[5] * 18.0f), 0), 18);
        int gc = min(max((int)(cf[6] * 18.0f), 0), 18);
        int tr = min(max((int)(cf[7] * 18.0f), 0), 18);
        int tc = min(max((int)(cf[8] * 18.0f), 0), 18);
        g_go[gw] = gr * 19 + gc;
        g_to[gw] = tr * 19 + tc;
    }
    float v0 = cf[lane * 2], v1 = cf[lane * 2 + 1];
    float r0, r1;
    uint32_t hp = pack_hi(v0, v1, r0, r1);
    uint32_t lp = pack_lo(r0, r1);
    size_t tb = (size_t)(gw >> 7) * A_IMG + swz((uint32_t)((gw & 127) * 128 + lane * 4));
    *reinterpret_cast<uint32_t*>(g_Xc_hi + tb) = hp;
    *reinterpret_cast<uint32_t*>(g_Xc_lo + tb) = lp;
}

// ---------------------------------------------------------------------------
// Prep 3: split W1c (rows 768..831) and W2 into K-major split-bf16 images.
// ---------------------------------------------------------------------------
__global__ void splitW_kernel(const float* __restrict__ W1, const float* __restrict__ W2) {
    int gw = (blockIdx.x * blockDim.x + threadIdx.x) >> 5;
    int lane = threadIdx.x & 31;
    if (gw < HID) {                       // W1c: warp per output column n
        int n = gw;
        int k = lane * 2;
        float w0 = W1[(size_t)(768 + k) * HID + n];
        float w1 = W1[(size_t)(769 + k) * HID + n];
        float r0, r1;
        uint32_t hp = pack_hi(w0, w1, r0, r1);
        uint32_t lp = pack_lo(r0, r1);
        size_t tb = (size_t)(n >> 8) * B_IMG + swz((uint32_t)((n & 255) * 128 + lane * 4));
        *reinterpret_cast<uint32_t*>(g_W1c_hi + tb) = hp;
        *reinterpret_cast<uint32_t*>(g_W1c_lo + tb) = lp;
    } else if (gw < 2 * HID) {            // W2: warp per column n, 16 chunks
        int n = gw - HID;
        size_t base = (size_t)(n >> 8) * NCH2 * B_IMG;
        uint32_t off = swz((uint32_t)((n & 255) * 128 + lane * 4));
        #pragma unroll
        for (int ch = 0; ch < NCH2; ch++) {
            int k0 = ch * KCH + lane * 2;
            float w0 = W2[(size_t)k0 * HID + n];
            float w1 = W2[(size_t)(k0 + 1) * HID + n];
            float r0, r1;
            uint32_t hp = pack_hi(w0, w1, r0, r1);
            uint32_t lp = pack_lo(r0, r1);
            *reinterpret_cast<uint32_t*>(g_W2t_hi + base + (size_t)ch * B_IMG + off) = hp;
            *reinterpret_cast<uint32_t*>(g_W2t_lo + base + (size_t)ch * B_IMG + off) = lp;
        }
    }
}

// ---------------------------------------------------------------------------
// Prep 4: P tables (fp32, exact).  grid (97, 4), block 256.
//   gx 0..47:  go rows  P[p]      = pf_t[p]   . W1[0:256]
//   gx 48..95: to rows  P[384+p]  = pf_t[p]   . W1[256:512]
//   gx 96:     gvec     = b1 + gp . W1[512:768]
// Unrolled x4 over c for MLP (R10 was load-latency bound at MLP=1).
// ---------------------------------------------------------------------------
__global__ void pgemm_kernel(const float* __restrict__ W1, const float* __restrict__ b1) {
    int n = blockIdx.y * 256 + threadIdx.x;
    int gx = blockIdx.x;
    if (gx == 96) {
        float s = b1[n];
        #pragma unroll 4
        for (int c = 0; c < 256; c++)
            s = fmaf(g_gpool[c], W1[(size_t)(512 + c) * HID + n], s);
        g_gvec[n] = s;
        return;
    }
    int isto = gx >= 48;
    int r0 = (isto ? gx - 48 : gx) * 8;
    const float* Wb = W1 + (size_t)(isto ? 256 : 0) * HID;
    const float* pfr[8];
    #pragma unroll
    for (int rr = 0; rr < 8; rr++) pfr[rr] = g_pf_t + (size_t)min(r0 + rr, 360) * 256;
    float acc[8] = {0, 0, 0, 0, 0, 0, 0, 0};
    for (int c = 0; c < 256; c += 4) {
        float w0 = Wb[(size_t)(c + 0) * HID + n];
        float w1 = Wb[(size_t)(c + 1) * HID + n];
        float w2 = Wb[(size_t)(c + 2) * HID + n];
        float w3 = Wb[(size_t)(c + 3) * HID + n];
        #pragma unroll
        for (int rr = 0; rr < 8; rr++) {
            acc[rr] = fmaf(pfr[rr][c + 0], w0, acc[rr]);
            acc[rr] = fmaf(pfr[rr][c + 1], w1, acc[rr]);
            acc[rr] = fmaf(pfr[rr][c + 2], w2, acc[rr]);
            acc[rr] = fmaf(pfr[rr][c + 3], w3, acc[rr]);
        }
    }
    #pragma unroll
    for (int rr = 0; rr < 8; rr++) {
        int p = r0 + rr;
        if (p < BOARD_SQ) g_P[(size_t)(isto ? 384 + p : p) * HID + n] = acc[rr];
    }
}

// ---------------------------------------------------------------------------
// GEMM: D[128x256] = A[128xK] * B[256xK]^T, 3-pass split bf16, bulk staging.
// 16 warps: warp grid 4(M) x 4(N), warp tile 32x64.
// MODE 0: A=Xc (K=64), B=W1c; epilogue adds P_go/P_to/gvec, relu -> H images
// MODE 1: A=Ht (K=1024), B=W2t; epilogue bias+relu+W3 dot partials
// ---------------------------------------------------------------------------
template <int MODE>
__global__ __launch_bounds__(THREADS, 1)
void gemm_kernel(const float* __restrict__ bias, const float* __restrict__ W3) {
    constexpr int NCH = MODE ? NCH2 : 1;
    extern __shared__ char smem[];
    const uint32_t smem_u = smem_u32(smem);
    const uint32_t stage0 = smem_u + 1024;
    const int tid = threadIdx.x;
    const int wid = tid >> 5, lid = tid & 31;
    const int wm = wid >> 2, wn = wid & 3;          // warp grid 4(M) x 4(N)
    const int nbase = blockIdx.x * N_TILE;
    const int mbase = blockIdx.y * M_TILE;
    const int g = lid >> 2, t = lid & 3;

    const unsigned char* At_h = MODE ? g_Ht_hi + (size_t)blockIdx.y * NCH2 * A_IMG
                                     : g_Xc_hi + (size_t)blockIdx.y * A_IMG;
    const unsigned char* At_l = MODE ? g_Ht_lo + (size_t)blockIdx.y * NCH2 * A_IMG
                                     : g_Xc_lo + (size_t)blockIdx.y * A_IMG;
    const unsigned char* Bt_h = MODE ? g_W2t_hi + (size_t)blockIdx.x * NCH2 * B_IMG
                                     : g_W1c_hi + (size_t)blockIdx.x * B_IMG;
    const unsigned char* Bt_l = MODE ? g_W2t_lo + (size_t)blockIdx.x * NCH2 * B_IMG
                                     : g_W1c_lo + (size_t)blockIdx.x * B_IMG;

    if (tid == 0) { MBARRIER_INIT(smem_u, 1); MBARRIER_INIT(smem_u + 8, 1); }
    FENCE_PROXY_ASYNC();
    __syncthreads();

    auto issue = [&](int stg, int kt) {
        if (tid == 0) {
            uint32_t mb = smem_u + stg * 8;
            uint32_t sb = stage0 + stg * STAGE_BYTES;
            MBARRIER_EXPECT_TX(mb, STAGE_BYTES);
            bulk_g2s(sb,             At_h + (size_t)kt * A_IMG, A_IMG, mb);
            bulk_g2s(sb + A_IMG,     At_l + (size_t)kt * A_IMG, A_IMG, mb);
            bulk_g2s(sb + 2 * A_IMG, Bt_h + (size_t)kt * B_IMG, B_IMG, mb);
            bulk_g2s(sb + 2 * A_IMG + B_IMG, Bt_l + (size_t)kt * B_IMG, B_IMG, mb);
        }
    };

    float acc[2][8][4];
    #pragma unroll
    for (int i = 0; i < 2; i++)
        #pragma unroll
        for (int j = 0; j < 8; j++)
            #pragma unroll
            for (int q = 0; q < 4; q++) acc[i][j][q] = 0.f;

    issue(0, 0);

    const int rlo = lid & 15;
    const uint32_t khalf16 = (uint32_t)((lid >> 4) * 16);

    for (int kt = 0; kt < NCH; kt++) {
        if (kt + 1 < NCH) issue((kt + 1) & 1, kt + 1);
        MBARRIER_WAIT_PARITY(smem_u + (kt & 1) * 8, (kt >> 1) & 1);

        const uint32_t sb = stage0 + (kt & 1) * STAGE_BYTES;
        #pragma unroll
        for (int s = 0; s < 4; s++) {
            const uint32_t kb = (uint32_t)(s * 32) + khalf16;
            uint32_t Af[2][4], Bx[4][4], By[4][4];
            #pragma unroll
            for (int i = 0; i < 2; i++) {            // A-hi frags (warp rows)
                uint32_t a = sb + swz((uint32_t)((wm * 32 + i * 16 + rlo) * 128) + kb);
                ldsm_x4(Af[i][0], Af[i][1], Af[i][2], Af[i][3], a);
            }
            #pragma unroll
            for (int jj = 0; jj < 4; jj++) {         // B-hi / B-lo frags
                uint32_t ro = swz((uint32_t)((wn * 64 + jj * 16 + rlo) * 128) + kb);
                ldsm_x4(Bx[jj][0], Bx[jj][1], Bx[jj][2], Bx[jj][3],
                        sb + 2 * A_IMG + ro);
                ldsm_x4(By[jj][0], By[jj][1], By[jj][2], By[jj][3],
                        sb + 2 * A_IMG + B_IMG + ro);
            }
            // pass 1: Ah*Bh, pass 2: Ah*Bl
            #pragma unroll
            for (int i = 0; i < 2; i++)
                #pragma unroll
                for (int jj = 0; jj < 4; jj++) {
                    mma_bf16(acc[i][2*jj],   Af[i][0],Af[i][1],Af[i][2],Af[i][3], Bx[jj][0], Bx[jj][2]);
                    mma_bf16(acc[i][2*jj+1], Af[i][0],Af[i][1],Af[i][2],Af[i][3], Bx[jj][1], Bx[jj][3]);
                    mma_bf16(acc[i][2*jj],   Af[i][0],Af[i][1],Af[i][2],Af[i][3], By[jj][0], By[jj][2]);
                    mma_bf16(acc[i][2*jj+1], Af[i][0],Af[i][1],Af[i][2],Af[i][3], By[jj][1], By[jj][3]);
                }
            // pass 3: Al*Bh (reuse Af regs)
            #pragma unroll
            for (int i = 0; i < 2; i++) {
                uint32_t a = sb + A_IMG + swz((uint32_t)((wm * 32 + i * 16 + rlo) * 128) + kb);
                ldsm_x4(Af[i][0], Af[i][1], Af[i][2], Af[i][3], a);
            }
            #pragma unroll
            for (int i = 0; i < 2; i++)
                #pragma unroll
                for (int jj = 0; jj < 4; jj++) {
                    mma_bf16(acc[i][2*jj],   Af[i][0],Af[i][1],Af[i][2],Af[i][3], Bx[jj][0], Bx[jj][2]);
                    mma_bf16(acc[i][2*jj+1], Af[i][0],Af[i][1],Af[i][2],Af[i][3], Bx[jj][1], Bx[jj][3]);
                }
        }
        __syncthreads();
    }

    // ------------------------------ epilogue ------------------------------
    if (MODE == 0) {
        #pragma unroll
        for (int i = 0; i < 2; i++) {
            #pragma unroll
            for (int h2 = 0; h2 < 2; h2++) {
                int m0 = mbase + wm * 32 + i * 16 + g + 8 * h2;
                const float* Pg = g_P + (size_t)g_go[m0] * HID;
                const float* Pt = g_P + (size_t)(384 + g_to[m0]) * HID;
                #pragma unroll
                for (int j = 0; j < 8; j++) {
                    int n0 = nbase + wn * 64 + j * 8 + 2 * t;
                    float v0 = acc[i][j][2*h2]     + Pg[n0]     + Pt[n0]     + g_gvec[n0];
                    float v1 = acc[i][j][2*h2 + 1] + Pg[n0 + 1] + Pt[n0 + 1] + g_gvec[n0 + 1];
                    v0 = fmaxf(v0, 0.f); v1 = fmaxf(v1, 0.f);
                    float r0, r1;
                    uint32_t hp = pack_hi(v0, v1, r0, r1);
                    uint32_t lp = pack_lo(r0, r1);
                    size_t tb = ((size_t)(m0 >> 7) * NCH2 + (n0 >> 6)) * A_IMG
                              + swz((uint32_t)((m0 & 127) * 128 + (n0 & 63) * 2));
                    *reinterpret_cast<uint32_t*>(g_Ht_hi + tb) = hp;
                    *reinterpret_cast<uint32_t*>(g_Ht_lo + tb) = lp;
                }
            }
        }
    } else {
        __syncthreads();                       // stages dead; overlay reducer
        float (*red)[4] = reinterpret_cast<float(*)[4]>(smem + 1024);
        #pragma unroll
        for (int i = 0; i < 2; i++) {
            float d0 = 0.f, d1 = 0.f;
            #pragma unroll
            for (int j = 0; j < 8; j++) {
                int n0 = nbase + wn * 64 + j * 8 + 2 * t;
                float bb0 = __ldg(&bias[n0]), bb1 = __ldg(&bias[n0 + 1]);
                float w0 = __ldg(&W3[n0]),   w1 = __ldg(&W3[n0 + 1]);
                d0 += fmaxf(acc[i][j][0] + bb0, 0.f) * w0 + fmaxf(acc[i][j][1] + bb1, 0.f) * w1;
                d1 += fmaxf(acc[i][j][2] + bb0, 0.f) * w0 + fmaxf(acc[i][j][3] + bb1, 0.f) * w1;
            }
            d0 += __shfl_xor_sync(0xffffffffu, d0, 1);
            d0 += __shfl_xor_sync(0xffffffffu, d0, 2);
            d1 += __shfl_xor_sync(0xffffffffu, d1, 1);
            d1 += __shfl_xor_sync(0xffffffffu, d1, 2);
            if (t == 0) {
                red[wm * 32 + i * 16 + g][wn]     = d0;
                red[wm * 32 + i * 16 + g + 8][wn] = d1;
            }
        }
        __syncthreads();
        if (tid < M_TILE) {
            float s = red[tid][0] + red[tid][1] + red[tid][2] + red[tid][3];
            g_part[(size_t)blockIdx.x * N_CAND + mbase + tid] = s;
        }
    }
}

// ---------------------------------------------------------------------------
// Final reduce: out[m] = b3 + sum over 4 n-tile partials (deterministic)
// ---------------------------------------------------------------------------
__global__ void reduce_kernel(const float* __restrict__ b3, float* __restrict__ out) {
    int m = blockIdx.x * blockDim.x + threadIdx.x;
    if (m < N_CAND) {
        float s = b3[0];
        #pragma unroll
        for (int tt = 0; tt < N_NT; tt++) s += g_part[(size_t)tt * N_CAND + m];
        out[m] = s;
    }
}

// ---------------------------------------------------------------------------
// Launch
// ---------------------------------------------------------------------------
extern "C" void kernel_launch(void* const* d_in, const int* in_sizes, int n_in,
                              void* d_out, int out_size) {
    const float* pf   = (const float*)d_in[0];   // (256,19,19)
    const float* cand = (const float*)d_in[1];   // (65536,64)
    const float* W1   = (const float*)d_in[2];   // (832,1024)
    const float* b1   = (const float*)d_in[3];
    const float* W2   = (const float*)d_in[4];   // (1024,1024)
    const float* b2   = (const float*)d_in[5];
    const float* W3   = (const float*)d_in[6];   // (1024,1)
    const float* b3   = (const float*)d_in[7];
    float* out = (float*)d_out;
    (void)in_sizes; (void)n_in; (void)out_size;

    (void)cudaFuncSetAttribute(gemm_kernel<0>,
                               cudaFuncAttributeMaxDynamicSharedMemorySize, SMEM_TOTAL);
    (void)cudaFuncSetAttribute(gemm_kernel<1>,
                               cudaFuncAttributeMaxDynamicSharedMemorySize, SMEM_TOTAL);

    prep_pf_kernel<<<BOARD_SQ + 1, 256>>>(pf);
    decode_buildXc_kernel<<<N_CAND / 8, 256>>>(cand);
    splitW_kernel<<<(2 * HID * 32) / 256, 256>>>(W1, W2);
    pgemm_kernel<<<dim3(97, 4), 256>>>(W1, b1);

    dim3 grid(N_NT, N_CAND / M_TILE);            // (4, 512)
    gemm_kernel<0><<<grid, THREADS, SMEM_TOTAL>>>(b1, nullptr);   // layer 1 (cand GEMM + gather)
    gemm_kernel<1><<<grid, THREADS, SMEM_TOTAL>>>(b2, W3);        // layer 2 + fused W3

    reduce_kernel<<<(N_CAND + 255) / 256, 256>>>(b3, out);
}